// round 6
// baseline (speedup 1.0000x reference)
#include <cuda_runtime.h>
#include <mma.h>
#include <math.h>

using namespace nvcuda;

#define IN_DIM 256
#define HID 128
#define OUTD 64
#define NMAX 50176
#define EMAX 800000

// ---------------- scratch (static device globals; no allocation) ----------------
__device__ int g_is64;                 // 1 if edge_index is int64, 0 if int32
__device__ __align__(16) int   g_src[EMAX];
__device__ __align__(16) int   g_dst[EMAX];
__device__ __align__(16) int   g_cnt[NMAX];
__device__ __align__(16) int   g_locpre[NMAX];   // block-local exclusive prefix
__device__ __align__(16) int   g_bsum[256];      // per-block sums
__device__ __align__(16) int   g_boff[256];      // scanned block offsets
__device__ __align__(16) int   g_rowptr[NMAX + 1];
__device__ __align__(16) int   g_cursor[NMAX];
__device__ __align__(16) int   g_col[EMAX];
__device__ __align__(16) float g_dinv[NMAX];
__device__ __align__(16) float g_t1[(size_t)NMAX * HID];   // x@W1 (unscaled)
__device__ __align__(16) float g_h1[(size_t)NMAX * HID];   // relu(gcn1)
__device__ __align__(16) float g_t2[(size_t)NMAX * OUTD];  // h1@W2 (unscaled)

// ---------------- edge width detection ----------------
__global__ void detect_kernel(const int* __restrict__ raw, int E) {
    __shared__ int s_nz;
    if (threadIdx.x == 0) s_nz = 0;
    __syncthreads();
    int i = threadIdx.x;
    if (i < E && raw[2 * i + 1] != 0) atomicOr(&s_nz, 1);
    __syncthreads();
    if (threadIdx.x == 0) g_is64 = (s_nz == 0) ? 1 : 0;
}

__global__ void zero_cnt_kernel(int n) {
    int i = blockIdx.x * blockDim.x + threadIdx.x;
    if (i < n) g_cnt[i] = 0;
}

__global__ void convert_hist_kernel(const int* __restrict__ raw, int E) {
    int i = blockIdx.x * blockDim.x + threadIdx.x;
    if (i >= E) return;
    int s, d;
    if (g_is64) {
        s = raw[2 * i];
        d = raw[2 * E + 2 * i];
    } else {
        s = raw[i];
        d = raw[E + i];
    }
    g_src[i] = s;
    g_dst[i] = d;
    atomicAdd(&g_cnt[d], 1);
}

// ---------------- multi-block exclusive scan (3 phases) ----------------
__global__ void scan_phase1(int n) {
    __shared__ int sh[256];
    int t = threadIdx.x;
    int i = blockIdx.x * 256 + t;
    int v = (i < n) ? g_cnt[i] : 0;
    sh[t] = v;
    __syncthreads();
#pragma unroll
    for (int off = 1; off < 256; off <<= 1) {
        int u = (t >= off) ? sh[t - off] : 0;
        __syncthreads();
        sh[t] += u;
        __syncthreads();
    }
    if (i < n) g_locpre[i] = sh[t] - v;   // exclusive
    if (t == 255) g_bsum[blockIdx.x] = sh[255];
}

__global__ void scan_phase2(int nb) {
    __shared__ int sh[256];
    int t = threadIdx.x;
    int v = (t < nb) ? g_bsum[t] : 0;
    sh[t] = v;
    __syncthreads();
#pragma unroll
    for (int off = 1; off < 256; off <<= 1) {
        int u = (t >= off) ? sh[t - off] : 0;
        __syncthreads();
        sh[t] += u;
        __syncthreads();
    }
    if (t < nb) g_boff[t] = sh[t] - v;
}

__global__ void scan_phase3(int n, int E) {
    int i = blockIdx.x * blockDim.x + threadIdx.x;
    if (i < n) {
        int rp = g_boff[i >> 8] + g_locpre[i];
        g_rowptr[i] = rp;
        g_cursor[i] = rp;
        g_dinv[i]   = rsqrtf((float)g_cnt[i] + 1.0f);  // +1 self loop
    }
    if (i == 0) g_rowptr[n] = E;
}

__global__ void scatter_kernel(int E) {
    int i = blockIdx.x * blockDim.x + threadIdx.x;
    if (i < E) {
        int pos = atomicAdd(&g_cursor[g_dst[i]], 1);
        g_col[pos] = g_src[i];
    }
}

// ---------------- tf32 WMMA GEMM: C[M,BN] = A[M,K] @ B[K,BN] ----------------
// 256 threads = 8 warps as 4(M) x 2(N). Warp tile: 32 x (BN/2).
// C rows are NOT bounds-checked: C is a scratch global padded to NMAX rows,
// and grid*BM <= NMAX. A loads ARE guarded (x has exactly M rows).
template <int BM, int BN, int BK, int LAYER>
__global__ void gemm_tf32(const float* __restrict__ A_in, const float* __restrict__ B,
                          int M, int K) {
    const float* __restrict__ A = (LAYER == 0) ? A_in : g_h1;
    float* __restrict__ C       = (LAYER == 0) ? g_t1 : g_t2;
    constexpr int N = BN;          // single column block covers full N
    constexpr int LDA = BK + 8;
    constexpr int LDB = BN + 8;
    constexpr int WN = BN / 2;     // warp tile N
    constexpr int MF = 2;          // 32/16 m-frags per warp
    constexpr int NF = WN / 16;    // n-frags per warp

    __shared__ float As[BM * LDA];
    __shared__ float Bs[BK * LDB];

    int tid = threadIdx.x;
    int wid = tid >> 5;
    int wm = wid & 3;              // 0..3  (M direction)
    int wn = wid >> 2;             // 0..1  (N direction)
    int row0 = blockIdx.x * BM;

    wmma::fragment<wmma::accumulator, 16, 16, 8, float> acc[MF][NF];
#pragma unroll
    for (int i = 0; i < MF; i++)
#pragma unroll
        for (int j = 0; j < NF; j++) wmma::fill_fragment(acc[i][j], 0.0f);

    for (int kt = 0; kt < K; kt += BK) {
        // A tile: BM x BK, guarded rows, tf32-converted
        constexpr int A4 = BM * BK / 4;
#pragma unroll
        for (int l = tid; l < A4; l += 256) {
            int r  = l / (BK / 4);
            int kq = l % (BK / 4);
            float4 v = make_float4(0.f, 0.f, 0.f, 0.f);
            if (row0 + r < M) v = *(const float4*)&A[(size_t)(row0 + r) * K + kt + kq * 4];
            float* dst = &As[r * LDA + kq * 4];
            dst[0] = wmma::__float_to_tf32(v.x);
            dst[1] = wmma::__float_to_tf32(v.y);
            dst[2] = wmma::__float_to_tf32(v.z);
            dst[3] = wmma::__float_to_tf32(v.w);
        }
        // B tile: BK x BN (B is K x N row-major, N == BN)
        constexpr int B4 = BK * BN / 4;
#pragma unroll
        for (int l = tid; l < B4; l += 256) {
            int k  = l / (BN / 4);
            int cq = l % (BN / 4);
            float4 v = *(const float4*)&B[(size_t)(kt + k) * BN + cq * 4];
            float* dst = &Bs[k * LDB + cq * 4];
            dst[0] = wmma::__float_to_tf32(v.x);
            dst[1] = wmma::__float_to_tf32(v.y);
            dst[2] = wmma::__float_to_tf32(v.z);
            dst[3] = wmma::__float_to_tf32(v.w);
        }
        __syncthreads();

#pragma unroll
        for (int ks = 0; ks < BK; ks += 8) {
            wmma::fragment<wmma::matrix_a, 16, 16, 8, wmma::precision::tf32, wmma::row_major> af[MF];
            wmma::fragment<wmma::matrix_b, 16, 16, 8, wmma::precision::tf32, wmma::row_major> bf[NF];
#pragma unroll
            for (int i = 0; i < MF; i++)
                wmma::load_matrix_sync(af[i], &As[(wm * 32 + i * 16) * LDA + ks], LDA);
#pragma unroll
            for (int j = 0; j < NF; j++)
                wmma::load_matrix_sync(bf[j], &Bs[ks * LDB + wn * WN + j * 16], LDB);
#pragma unroll
            for (int i = 0; i < MF; i++)
#pragma unroll
                for (int j = 0; j < NF; j++)
                    wmma::mma_sync(acc[i][j], af[i], bf[j], acc[i][j]);
        }
        __syncthreads();
    }

#pragma unroll
    for (int i = 0; i < MF; i++)
#pragma unroll
        for (int j = 0; j < NF; j++)
            wmma::store_matrix_sync(&C[(size_t)(row0 + wm * 32 + i * 16) * N + wn * WN + j * 16],
                                    acc[i][j], N, wmma::mem_row_major);
}

// ---------------- layer-1 aggregation: warp per node, 128 features ----------------
__global__ void agg1_kernel(const float* __restrict__ b1, int n) {
    int w = (blockIdx.x * blockDim.x + threadIdx.x) >> 5;
    int lane = threadIdx.x & 31;
    if (w >= n) return;
    const float4* g = (const float4*)g_t1;
    float di = g_dinv[w];
    float4 self = g[(size_t)w * 32 + lane];
    float4 acc;
    acc.x = self.x * di; acc.y = self.y * di; acc.z = self.z * di; acc.w = self.w * di;
    int e = g_rowptr[w], end = g_rowptr[w + 1];
    for (; e + 4 <= end; e += 4) {
        int s0 = g_col[e], s1 = g_col[e + 1], s2 = g_col[e + 2], s3 = g_col[e + 3];
        float d0 = g_dinv[s0], d1 = g_dinv[s1], d2 = g_dinv[s2], d3 = g_dinv[s3];
        float4 v0 = g[(size_t)s0 * 32 + lane];
        float4 v1 = g[(size_t)s1 * 32 + lane];
        float4 v2 = g[(size_t)s2 * 32 + lane];
        float4 v3 = g[(size_t)s3 * 32 + lane];
        acc.x = fmaf(v0.x, d0, fmaf(v1.x, d1, fmaf(v2.x, d2, fmaf(v3.x, d3, acc.x))));
        acc.y = fmaf(v0.y, d0, fmaf(v1.y, d1, fmaf(v2.y, d2, fmaf(v3.y, d3, acc.y))));
        acc.z = fmaf(v0.z, d0, fmaf(v1.z, d1, fmaf(v2.z, d2, fmaf(v3.z, d3, acc.z))));
        acc.w = fmaf(v0.w, d0, fmaf(v1.w, d1, fmaf(v2.w, d2, fmaf(v3.w, d3, acc.w))));
    }
    for (; e < end; e++) {
        int s = g_col[e];
        float ds = g_dinv[s];
        float4 v = g[(size_t)s * 32 + lane];
        acc.x = fmaf(v.x, ds, acc.x);
        acc.y = fmaf(v.y, ds, acc.y);
        acc.z = fmaf(v.z, ds, acc.z);
        acc.w = fmaf(v.w, ds, acc.w);
    }
    float4 b = ((const float4*)b1)[lane];
    float4 r;
    r.x = fmaxf(fmaf(acc.x, di, b.x), 0.f);
    r.y = fmaxf(fmaf(acc.y, di, b.y), 0.f);
    r.z = fmaxf(fmaf(acc.z, di, b.z), 0.f);
    r.w = fmaxf(fmaf(acc.w, di, b.w), 0.f);
    ((float4*)g_h1)[(size_t)w * 32 + lane] = r;
}

// ---------------- layer-2 aggregation + rule head + log_softmax ----------------
__global__ void agg2_final_kernel(const float* __restrict__ b2,
                                  const float* __restrict__ We,
                                  const float* __restrict__ be,
                                  const float* __restrict__ Wg,
                                  const float* __restrict__ bg,
                                  const float* __restrict__ rw,
                                  float* __restrict__ out, int n) {
    int w = (blockIdx.x * blockDim.x + threadIdx.x) >> 5;
    int lane = threadIdx.x & 31;
    if (w >= n) return;
    const float2* g = (const float2*)g_t2;
    float di = g_dinv[w];
    float2 self = g[(size_t)w * 32 + lane];
    float2 acc;
    acc.x = self.x * di; acc.y = self.y * di;
    int e = g_rowptr[w], end = g_rowptr[w + 1];
    for (; e + 4 <= end; e += 4) {
        int s0 = g_col[e], s1 = g_col[e + 1], s2 = g_col[e + 2], s3 = g_col[e + 3];
        float d0 = g_dinv[s0], d1 = g_dinv[s1], d2 = g_dinv[s2], d3 = g_dinv[s3];
        float2 v0 = g[(size_t)s0 * 32 + lane];
        float2 v1 = g[(size_t)s1 * 32 + lane];
        float2 v2 = g[(size_t)s2 * 32 + lane];
        float2 v3 = g[(size_t)s3 * 32 + lane];
        acc.x = fmaf(v0.x, d0, fmaf(v1.x, d1, fmaf(v2.x, d2, fmaf(v3.x, d3, acc.x))));
        acc.y = fmaf(v0.y, d0, fmaf(v1.y, d1, fmaf(v2.y, d2, fmaf(v3.y, d3, acc.y))));
    }
    for (; e < end; e++) {
        int s = g_col[e];
        float ds = g_dinv[s];
        float2 v = g[(size_t)s * 32 + lane];
        acc.x = fmaf(v.x, ds, acc.x);
        acc.y = fmaf(v.y, ds, acc.y);
    }
    float2 b = ((const float2*)b2)[lane];
    float hx = fmaf(acc.x, di, b.x);
    float hy = fmaf(acc.y, di, b.y);

    // rule_out = h @ We + be (We: [64,3] row-major); lane holds cols 2*lane, 2*lane+1
    int c0 = 2 * lane;
    float p0 = hx * We[c0 * 3 + 0] + hy * We[c0 * 3 + 3];
    float p1 = hx * We[c0 * 3 + 1] + hy * We[c0 * 3 + 4];
    float p2 = hx * We[c0 * 3 + 2] + hy * We[c0 * 3 + 5];
#pragma unroll
    for (int off = 16; off; off >>= 1) {
        p0 += __shfl_xor_sync(0xffffffff, p0, off);
        p1 += __shfl_xor_sync(0xffffffff, p1, off);
        p2 += __shfl_xor_sync(0xffffffff, p2, off);
    }
    float r0 = p0 + be[0], r1 = p1 + be[1], r2 = p2 + be[2];
    float z = r0 * Wg[0] + r1 * Wg[1] + r2 * Wg[2] + bg[0];
    float gate = 1.0f / (1.0f + expf(-z));
    float add = gate * rw[0];
    hx += add;
    hy += add;

    // log_softmax over the 64 features
    float m = fmaxf(hx, hy);
#pragma unroll
    for (int off = 16; off; off >>= 1) m = fmaxf(m, __shfl_xor_sync(0xffffffff, m, off));
    float se = expf(hx - m) + expf(hy - m);
#pragma unroll
    for (int off = 16; off; off >>= 1) se += __shfl_xor_sync(0xffffffff, se, off);
    float ls = logf(se);

    float2 o;
    o.x = hx - m - ls;
    o.y = hy - m - ls;
    ((float2*)out)[(size_t)w * 32 + lane] = o;
}

// ---------------- launch (fork-join: CSR chain overlaps GEMM1) ----------------
extern "C" void kernel_launch(void* const* d_in, const int* in_sizes, int n_in,
                              void* d_out, int out_size) {
    const float* x   = (const float*)d_in[0];
    const int*   ei  = (const int*)d_in[1];
    // d_in[2] = rules (unused by the math)
    const float* W1 = (const float*)d_in[3];
    const float* b1 = (const float*)d_in[4];
    const float* W2 = (const float*)d_in[5];
    const float* b2 = (const float*)d_in[6];
    const float* We = (const float*)d_in[7];
    const float* be = (const float*)d_in[8];
    const float* Wg = (const float*)d_in[9];
    const float* bg = (const float*)d_in[10];
    const float* rw = (const float*)d_in[11];

    int n = in_sizes[0] / IN_DIM;
    int E = in_sizes[1] / 2;
    int nb = (n + 255) / 256;

    cudaStream_t s2;
    cudaStreamCreate(&s2);
    cudaEvent_t evFork, evJoin;
    cudaEventCreateWithFlags(&evFork, cudaEventDisableTiming);
    cudaEventCreateWithFlags(&evJoin, cudaEventDisableTiming);

    cudaEventRecord(evFork, 0);
    cudaStreamWaitEvent(s2, evFork, 0);

    detect_kernel<<<1, 256, 0, s2>>>(ei, E);
    zero_cnt_kernel<<<(n + 255) / 256, 256, 0, s2>>>(n);
    convert_hist_kernel<<<(E + 255) / 256, 256, 0, s2>>>(ei, E);
    scan_phase1<<<nb, 256, 0, s2>>>(n);
    scan_phase2<<<1, 256, 0, s2>>>(nb);
    scan_phase3<<<(n + 255) / 256, 256, 0, s2>>>(n, E);
    scatter_kernel<<<(E + 255) / 256, 256, 0, s2>>>(E);

    // layer-1 GEMM (tensor cores, graph-independent)
    gemm_tf32<128, 128, 32, 0><<<(n + 127) / 128, 256>>>(x, W1, n, IN_DIM);

    cudaEventRecord(evJoin, s2);
    cudaStreamWaitEvent(0, evJoin, 0);

    agg1_kernel<<<(n * 32 + 255) / 256, 256>>>(b1, n);
    gemm_tf32<128, 64, 32, 1><<<(n + 127) / 128, 256>>>(nullptr, W2, n, HID);
    agg2_final_kernel<<<(n * 32 + 255) / 256, 256>>>(b2, We, be, Wg, bg, rw, (float*)d_out, n);

    cudaEventDestroy(evFork);
    cudaEventDestroy(evJoin);
    cudaStreamDestroy(s2);
}

// round 7
// speedup vs baseline: 1.4431x; 1.4431x over previous
#include <cuda_runtime.h>
#include <cuda_bf16.h>
#include <mma.h>
#include <math.h>

using namespace nvcuda;

#define IN_DIM 256
#define HID 128
#define OUTD 64
#define NMAX 50176
#define EMAX 800000

// ---------------- scratch (static device globals; no allocation) ----------------
__device__ int g_is64;                 // 1 if edge_index is int64, 0 if int32
__device__ __align__(16) int   g_src[EMAX];
__device__ __align__(16) int   g_dst[EMAX];
__device__ __align__(16) int   g_cnt[NMAX];
__device__ __align__(16) int   g_locpre[NMAX];   // block-local exclusive prefix
__device__ __align__(16) int   g_bsum[256];      // per-block sums
__device__ __align__(16) int   g_boff[256];      // scanned block offsets
__device__ __align__(16) int   g_rowptr[NMAX + 1];
__device__ __align__(16) int   g_cursor[NMAX];
__device__ __align__(16) int   g_col[EMAX];
__device__ __align__(16) float g_dinv[NMAX];
__device__ __align__(16) float g_t1[(size_t)NMAX * HID];   // x@W1 (unscaled)
__device__ __align__(16) float g_h1[(size_t)NMAX * HID];   // relu(gcn1)
__device__ __align__(16) float g_t2[(size_t)NMAX * OUTD];  // h1@W2 (unscaled)

// ---------------- edge width detection ----------------
__global__ void detect_kernel(const int* __restrict__ raw, int E) {
    __shared__ int s_nz;
    if (threadIdx.x == 0) s_nz = 0;
    __syncthreads();
    int i = threadIdx.x;
    if (i < E && raw[2 * i + 1] != 0) atomicOr(&s_nz, 1);
    __syncthreads();
    if (threadIdx.x == 0) g_is64 = (s_nz == 0) ? 1 : 0;
}

__global__ void zero_cnt_kernel(int n) {
    int i = blockIdx.x * blockDim.x + threadIdx.x;
    if (i < n) g_cnt[i] = 0;
}

__global__ void convert_hist_kernel(const int* __restrict__ raw, int E) {
    int i = blockIdx.x * blockDim.x + threadIdx.x;
    if (i >= E) return;
    int s, d;
    if (g_is64) {
        s = raw[2 * i];
        d = raw[2 * E + 2 * i];
    } else {
        s = raw[i];
        d = raw[E + i];
    }
    g_src[i] = s;
    g_dst[i] = d;
    atomicAdd(&g_cnt[d], 1);
}

// ---------------- multi-block exclusive scan (3 phases) ----------------
__global__ void scan_phase1(int n) {
    __shared__ int sh[256];
    int t = threadIdx.x;
    int i = blockIdx.x * 256 + t;
    int v = (i < n) ? g_cnt[i] : 0;
    sh[t] = v;
    __syncthreads();
#pragma unroll
    for (int off = 1; off < 256; off <<= 1) {
        int u = (t >= off) ? sh[t - off] : 0;
        __syncthreads();
        sh[t] += u;
        __syncthreads();
    }
    if (i < n) g_locpre[i] = sh[t] - v;   // exclusive
    if (t == 255) g_bsum[blockIdx.x] = sh[255];
}

__global__ void scan_phase2(int nb) {
    __shared__ int sh[256];
    int t = threadIdx.x;
    int v = (t < nb) ? g_bsum[t] : 0;
    sh[t] = v;
    __syncthreads();
#pragma unroll
    for (int off = 1; off < 256; off <<= 1) {
        int u = (t >= off) ? sh[t - off] : 0;
        __syncthreads();
        sh[t] += u;
        __syncthreads();
    }
    if (t < nb) g_boff[t] = sh[t] - v;
}

__global__ void scan_phase3(int n, int E) {
    int i = blockIdx.x * blockDim.x + threadIdx.x;
    if (i < n) {
        int rp = g_boff[i >> 8] + g_locpre[i];
        g_rowptr[i] = rp;
        g_cursor[i] = rp;
        g_dinv[i]   = rsqrtf((float)g_cnt[i] + 1.0f);  // +1 self loop
    }
    if (i == 0) g_rowptr[n] = E;
}

__global__ void scatter_kernel(int E) {
    int i = blockIdx.x * blockDim.x + threadIdx.x;
    if (i < E) {
        int pos = atomicAdd(&g_cursor[g_dst[i]], 1);
        g_col[pos] = g_src[i];
    }
}

// ---------------- bf16 WMMA GEMM: C[M,BN] = A[M,K] @ B[K,BN], fp32 accum ----------
// 128 threads = 4 warps as 2(M) x 2(N). Warp tile: 64 x (BN/2).
// C is scratch padded to NMAX rows (grid*BM == NMAX), so C stores are unguarded.
// A loads guarded by M. Inputs converted fp32 -> bf16 during the smem fill.
template <int BM, int BN, int BK, int LAYER>
__global__ void gemm_bf16(const float* __restrict__ A_in, const float* __restrict__ B,
                          int M, int K) {
    const float* __restrict__ A = (LAYER == 0) ? A_in : g_h1;
    float* __restrict__ C       = (LAYER == 0) ? g_t1 : g_t2;
    constexpr int N   = BN;
    constexpr int LDA = BK + 8;     // bf16 elems
    constexpr int LDB = BN + 8;
    constexpr int WM  = BM / 2;     // 64
    constexpr int WN  = BN / 2;     // 64 or 32
    constexpr int MF  = WM / 16;    // 4
    constexpr int NF  = WN / 16;    // 4 or 2

    __shared__ __nv_bfloat16 As[BM * LDA];
    __shared__ __nv_bfloat16 Bs[BK * LDB];

    int tid = threadIdx.x;
    int wid = tid >> 5;
    int wm = wid & 1;
    int wn = wid >> 1;
    int row0 = blockIdx.x * BM;

    wmma::fragment<wmma::accumulator, 16, 16, 16, float> acc[MF][NF];
#pragma unroll
    for (int i = 0; i < MF; i++)
#pragma unroll
        for (int j = 0; j < NF; j++) wmma::fill_fragment(acc[i][j], 0.0f);

    for (int kt = 0; kt < K; kt += BK) {
        // A tile: BM x BK fp32 -> bf16
        constexpr int A4 = BM * BK / 4;
#pragma unroll
        for (int l = tid; l < A4; l += 128) {
            int r  = l / (BK / 4);
            int kq = l % (BK / 4);
            float4 v = make_float4(0.f, 0.f, 0.f, 0.f);
            if (row0 + r < M) v = *(const float4*)&A[(size_t)(row0 + r) * K + kt + kq * 4];
            __nv_bfloat16* dst = &As[r * LDA + kq * 4];
            dst[0] = __float2bfloat16(v.x);
            dst[1] = __float2bfloat16(v.y);
            dst[2] = __float2bfloat16(v.z);
            dst[3] = __float2bfloat16(v.w);
        }
        // B tile: BK x BN fp32 -> bf16 (B is K x N row-major, N == BN)
        constexpr int B4 = BK * BN / 4;
#pragma unroll
        for (int l = tid; l < B4; l += 128) {
            int k  = l / (BN / 4);
            int cq = l % (BN / 4);
            float4 v = *(const float4*)&B[(size_t)(kt + k) * BN + cq * 4];
            __nv_bfloat16* dst = &Bs[k * LDB + cq * 4];
            dst[0] = __float2bfloat16(v.x);
            dst[1] = __float2bfloat16(v.y);
            dst[2] = __float2bfloat16(v.z);
            dst[3] = __float2bfloat16(v.w);
        }
        __syncthreads();

#pragma unroll
        for (int ks = 0; ks < BK; ks += 16) {
            wmma::fragment<wmma::matrix_a, 16, 16, 16, __nv_bfloat16, wmma::row_major> af[MF];
            wmma::fragment<wmma::matrix_b, 16, 16, 16, __nv_bfloat16, wmma::row_major> bf[NF];
#pragma unroll
            for (int i = 0; i < MF; i++)
                wmma::load_matrix_sync(af[i], &As[(wm * WM + i * 16) * LDA + ks], LDA);
#pragma unroll
            for (int j = 0; j < NF; j++)
                wmma::load_matrix_sync(bf[j], &Bs[ks * LDB + wn * WN + j * 16], LDB);
#pragma unroll
            for (int i = 0; i < MF; i++)
#pragma unroll
                for (int j = 0; j < NF; j++)
                    wmma::mma_sync(acc[i][j], af[i], bf[j], acc[i][j]);
        }
        __syncthreads();
    }

#pragma unroll
    for (int i = 0; i < MF; i++)
#pragma unroll
        for (int j = 0; j < NF; j++)
            wmma::store_matrix_sync(&C[(size_t)(row0 + wm * WM + i * 16) * N + wn * WN + j * 16],
                                    acc[i][j], N, wmma::mem_row_major);
}

// ---------------- layer-1 aggregation: warp per node, 128 features ----------------
__global__ void agg1_kernel(const float* __restrict__ b1, int n) {
    int w = (blockIdx.x * blockDim.x + threadIdx.x) >> 5;
    int lane = threadIdx.x & 31;
    if (w >= n) return;
    const float4* g = (const float4*)g_t1;
    float di = g_dinv[w];
    float4 self = g[(size_t)w * 32 + lane];
    float4 acc;
    acc.x = self.x * di; acc.y = self.y * di; acc.z = self.z * di; acc.w = self.w * di;
    int e = g_rowptr[w], end = g_rowptr[w + 1];
    for (; e + 4 <= end; e += 4) {
        int s0 = g_col[e], s1 = g_col[e + 1], s2 = g_col[e + 2], s3 = g_col[e + 3];
        float d0 = g_dinv[s0], d1 = g_dinv[s1], d2 = g_dinv[s2], d3 = g_dinv[s3];
        float4 v0 = g[(size_t)s0 * 32 + lane];
        float4 v1 = g[(size_t)s1 * 32 + lane];
        float4 v2 = g[(size_t)s2 * 32 + lane];
        float4 v3 = g[(size_t)s3 * 32 + lane];
        acc.x = fmaf(v0.x, d0, fmaf(v1.x, d1, fmaf(v2.x, d2, fmaf(v3.x, d3, acc.x))));
        acc.y = fmaf(v0.y, d0, fmaf(v1.y, d1, fmaf(v2.y, d2, fmaf(v3.y, d3, acc.y))));
        acc.z = fmaf(v0.z, d0, fmaf(v1.z, d1, fmaf(v2.z, d2, fmaf(v3.z, d3, acc.z))));
        acc.w = fmaf(v0.w, d0, fmaf(v1.w, d1, fmaf(v2.w, d2, fmaf(v3.w, d3, acc.w))));
    }
    for (; e < end; e++) {
        int s = g_col[e];
        float ds = g_dinv[s];
        float4 v = g[(size_t)s * 32 + lane];
        acc.x = fmaf(v.x, ds, acc.x);
        acc.y = fmaf(v.y, ds, acc.y);
        acc.z = fmaf(v.z, ds, acc.z);
        acc.w = fmaf(v.w, ds, acc.w);
    }
    float4 b = ((const float4*)b1)[lane];
    float4 r;
    r.x = fmaxf(fmaf(acc.x, di, b.x), 0.f);
    r.y = fmaxf(fmaf(acc.y, di, b.y), 0.f);
    r.z = fmaxf(fmaf(acc.z, di, b.z), 0.f);
    r.w = fmaxf(fmaf(acc.w, di, b.w), 0.f);
    ((float4*)g_h1)[(size_t)w * 32 + lane] = r;
}

// ---------------- layer-2 aggregation + rule head + log_softmax ----------------
__global__ void agg2_final_kernel(const float* __restrict__ b2,
                                  const float* __restrict__ We,
                                  const float* __restrict__ be,
                                  const float* __restrict__ Wg,
                                  const float* __restrict__ bg,
                                  const float* __restrict__ rw,
                                  float* __restrict__ out, int n) {
    int w = (blockIdx.x * blockDim.x + threadIdx.x) >> 5;
    int lane = threadIdx.x & 31;
    if (w >= n) return;
    const float2* g = (const float2*)g_t2;
    float di = g_dinv[w];
    float2 self = g[(size_t)w * 32 + lane];
    float2 acc;
    acc.x = self.x * di; acc.y = self.y * di;
    int e = g_rowptr[w], end = g_rowptr[w + 1];
    for (; e + 4 <= end; e += 4) {
        int s0 = g_col[e], s1 = g_col[e + 1], s2 = g_col[e + 2], s3 = g_col[e + 3];
        float d0 = g_dinv[s0], d1 = g_dinv[s1], d2 = g_dinv[s2], d3 = g_dinv[s3];
        float2 v0 = g[(size_t)s0 * 32 + lane];
        float2 v1 = g[(size_t)s1 * 32 + lane];
        float2 v2 = g[(size_t)s2 * 32 + lane];
        float2 v3 = g[(size_t)s3 * 32 + lane];
        acc.x = fmaf(v0.x, d0, fmaf(v1.x, d1, fmaf(v2.x, d2, fmaf(v3.x, d3, acc.x))));
        acc.y = fmaf(v0.y, d0, fmaf(v1.y, d1, fmaf(v2.y, d2, fmaf(v3.y, d3, acc.y))));
    }
    for (; e < end; e++) {
        int s = g_col[e];
        float ds = g_dinv[s];
        float2 v = g[(size_t)s * 32 + lane];
        acc.x = fmaf(v.x, ds, acc.x);
        acc.y = fmaf(v.y, ds, acc.y);
    }
    float2 b = ((const float2*)b2)[lane];
    float hx = fmaf(acc.x, di, b.x);
    float hy = fmaf(acc.y, di, b.y);

    // rule_out = h @ We + be (We: [64,3] row-major); lane holds cols 2*lane, 2*lane+1
    int c0 = 2 * lane;
    float p0 = hx * We[c0 * 3 + 0] + hy * We[c0 * 3 + 3];
    float p1 = hx * We[c0 * 3 + 1] + hy * We[c0 * 3 + 4];
    float p2 = hx * We[c0 * 3 + 2] + hy * We[c0 * 3 + 5];
#pragma unroll
    for (int off = 16; off; off >>= 1) {
        p0 += __shfl_xor_sync(0xffffffff, p0, off);
        p1 += __shfl_xor_sync(0xffffffff, p1, off);
        p2 += __shfl_xor_sync(0xffffffff, p2, off);
    }
    float r0 = p0 + be[0], r1 = p1 + be[1], r2 = p2 + be[2];
    float z = r0 * Wg[0] + r1 * Wg[1] + r2 * Wg[2] + bg[0];
    float gate = 1.0f / (1.0f + expf(-z));
    float add = gate * rw[0];
    hx += add;
    hy += add;

    // log_softmax over the 64 features
    float m = fmaxf(hx, hy);
#pragma unroll
    for (int off = 16; off; off >>= 1) m = fmaxf(m, __shfl_xor_sync(0xffffffff, m, off));
    float se = expf(hx - m) + expf(hy - m);
#pragma unroll
    for (int off = 16; off; off >>= 1) se += __shfl_xor_sync(0xffffffff, se, off);
    float ls = logf(se);

    float2 o;
    o.x = hx - m - ls;
    o.y = hy - m - ls;
    ((float2*)out)[(size_t)w * 32 + lane] = o;
}

// ---------------- launch (fork-join: CSR chain overlaps GEMM1) ----------------
extern "C" void kernel_launch(void* const* d_in, const int* in_sizes, int n_in,
                              void* d_out, int out_size) {
    const float* x   = (const float*)d_in[0];
    const int*   ei  = (const int*)d_in[1];
    // d_in[2] = rules (unused by the math)
    const float* W1 = (const float*)d_in[3];
    const float* b1 = (const float*)d_in[4];
    const float* W2 = (const float*)d_in[5];
    const float* b2 = (const float*)d_in[6];
    const float* We = (const float*)d_in[7];
    const float* be = (const float*)d_in[8];
    const float* Wg = (const float*)d_in[9];
    const float* bg = (const float*)d_in[10];
    const float* rw = (const float*)d_in[11];

    int n = in_sizes[0] / IN_DIM;
    int E = in_sizes[1] / 2;
    int nb = (n + 255) / 256;

    cudaStream_t s2;
    cudaStreamCreate(&s2);
    cudaEvent_t evFork, evJoin;
    cudaEventCreateWithFlags(&evFork, cudaEventDisableTiming);
    cudaEventCreateWithFlags(&evJoin, cudaEventDisableTiming);

    cudaEventRecord(evFork, 0);
    cudaStreamWaitEvent(s2, evFork, 0);

    detect_kernel<<<1, 256, 0, s2>>>(ei, E);
    zero_cnt_kernel<<<(n + 255) / 256, 256, 0, s2>>>(n);
    convert_hist_kernel<<<(E + 255) / 256, 256, 0, s2>>>(ei, E);
    scan_phase1<<<nb, 256, 0, s2>>>(n);
    scan_phase2<<<1, 256, 0, s2>>>(nb);
    scan_phase3<<<(n + 255) / 256, 256, 0, s2>>>(n, E);
    scatter_kernel<<<(E + 255) / 256, 256, 0, s2>>>(E);

    // layer-1 GEMM (bf16 tensor cores, graph-independent)
    gemm_bf16<128, 128, 32, 0><<<(n + 127) / 128, 128>>>(x, W1, n, IN_DIM);

    cudaEventRecord(evJoin, s2);
    cudaStreamWaitEvent(0, evJoin, 0);

    agg1_kernel<<<(n * 32 + 255) / 256, 256>>>(b1, n);
    gemm_bf16<128, 64, 32, 1><<<(n + 127) / 128, 128>>>(nullptr, W2, n, HID);
    agg2_final_kernel<<<(n * 32 + 255) / 256, 256>>>(b2, We, be, Wg, bg, rw, (float*)d_out, n);

    cudaEventDestroy(evFork);
    cudaEventDestroy(evJoin);
    cudaStreamDestroy(s2);
}